// round 13
// baseline (speedup 1.0000x reference)
#include <cuda_runtime.h>

#define BB 2
#define HH 512
#define WW 512
#define HW (HH*WW)            // 262144
#define CHW ((size_t)256*HW)
#define NPIX (BB*HW)          // 524288
#define GRID 256
#define TPB 256               // 65536 threads, 8 px each; block owns 4 rows

// ---------------- device scratch (static, no allocation) ----------------
__device__ unsigned char g_alpha[2][NPIX];         // boundary rows only
__device__ unsigned g_epoch;                       // bumped once per replay by k_init
__device__ unsigned long long g_mpart[GRID][2];    // tagged per-block {mn, mx}
__device__ unsigned long long g_spart[5][GRID][8]; // tagged per-block partials
                                                   // slot0: s0,s1,s2,cnt,t0,t1,t2
                                                   // slot1..4: s0,s1,s2,cnt

__device__ __forceinline__ unsigned f2ord(float f) {
    unsigned u = __float_as_uint(f);
    return (u & 0x80000000u) ? ~u : (u | 0x80000000u);
}
__device__ __forceinline__ float ord2f(unsigned u) {
    return __uint_as_float((u & 0x80000000u) ? (u ^ 0x80000000u) : ~u);
}
__device__ __forceinline__ float normq(float f, float mn, float den) {
    float v = __fmul_rn(__fdiv_rn(__fsub_rn(f, mn), den), 255.0f);
    v = floorf(v);
    return fminf(fmaxf(v, 0.0f), 255.0f);
}
__device__ __forceinline__ void st_rel64(unsigned long long* p, unsigned long long v) {
    asm volatile("st.release.gpu.global.u64 [%0], %1;"
                 :: "l"(__cvta_generic_to_global(p)), "l"(v) : "memory");
}
__device__ __forceinline__ unsigned long long ld_acq64(const unsigned long long* p) {
    unsigned long long v;
    asm volatile("ld.acquire.gpu.global.u64 %0, [%1];"
                 : "=l"(v) : "l"(__cvta_generic_to_global(p)) : "memory");
    return v;
}

// ---------------- kernel 0: bump epoch (tags become replay-unique) ----------------
__global__ void k_init() {
    if (threadIdx.x == 0) g_epoch = g_epoch + 1u;
}

// ---------------- whole pipeline, one persistent dataflow kernel ----------------
__global__ void __launch_bounds__(TPB, 2)
k_fused(const float* __restrict__ feat, const int* __restrict__ mask,
        float* __restrict__ out) {
    const int t    = threadIdx.x;
    const int lane = t & 31, warp = t >> 5;    // 8 warps
    const int bid  = blockIdx.x;
    const int tid  = bid * TPB + t;
    const int p0   = tid * 8;
    const int b    = p0 >> 18;
    const int r    = p0 & (HW - 1);
    const int y    = r >> 9;
    const int x0   = r & 511;
    const int ry   = t >> 6;                   // local row 0..3
    const int gbase = b << 7;                  // first block of this batch
    const bool has_up = (bid & 127) != 0;
    const bool has_dn = (bid & 127) != 127;
    const unsigned tbase = __ldcg(&g_epoch) << 4;   // 16 tags per replay

    __shared__ unsigned char s_alpha[2][4][512];    // double-buffered alpha tile
    __shared__ unsigned char s_halo[2][512];        // up/dn halo rows
    __shared__ unsigned s_su[7 * 8];
    __shared__ unsigned s_tot[8];                   // gathered global sums (persist)
    __shared__ float    s_means[8];
    __shared__ unsigned s_u[16];

    // trimap bitmasks for this thread's 8 px
    unsigned fixmask = 0, cenmask = 0;
    {
        bool yb = (y < 51) | (y >= 461);
        bool yc = (y >= 230) & (y < 281);
        #pragma unroll
        for (int j = 0; j < 8; j++) {
            int xj = x0 + j;
            bool border = yb | (xj < 51) | (xj >= 461);
            bool center = yc & (xj >= 230) & (xj < 281);
            fixmask |= (unsigned)(border | center) << j;
            cenmask |= (unsigned)center << j;
        }
    }

    // ======== phase 1: load pixels + mask; alpha0; publish tagged min/max ========
    const float* fb = feat + (size_t)b * CHW;
    float f0[8], f1[8], f2[8];
    {
        float4 v;
        v = *(const float4*)(fb + r);              f0[0]=v.x; f0[1]=v.y; f0[2]=v.z; f0[3]=v.w;
        v = *(const float4*)(fb + r + 4);          f0[4]=v.x; f0[5]=v.y; f0[6]=v.z; f0[7]=v.w;
        v = *(const float4*)(fb + HW + r);         f1[0]=v.x; f1[1]=v.y; f1[2]=v.z; f1[3]=v.w;
        v = *(const float4*)(fb + HW + r + 4);     f1[4]=v.x; f1[5]=v.y; f1[6]=v.z; f1[7]=v.w;
        v = *(const float4*)(fb + 2*HW + r);       f2[0]=v.x; f2[1]=v.y; f2[2]=v.z; f2[3]=v.w;
        v = *(const float4*)(fb + 2*HW + r + 4);   f2[4]=v.x; f2[5]=v.y; f2[6]=v.z; f2[7]=v.w;
    }
    unsigned al, ah;                        // own alpha, 8 bytes packed
    {
        int4 m0 = *(const int4*)(mask + p0);
        int4 m1 = *(const int4*)(mask + p0 + 4);
        unsigned mbits =
              (m0.x==1 ? 1u:0u) | (m0.y==1 ? 2u:0u) | (m0.z==1 ? 4u:0u) | (m0.w==1 ? 8u:0u)
            | (m1.x==1 ?16u:0u) | (m1.y==1 ?32u:0u) | (m1.z==1 ?64u:0u) | (m1.w==1?128u:0u);
        unsigned abits = (fixmask & cenmask) | (~fixmask & mbits);
        al = 0; ah = 0;
        #pragma unroll
        for (int j = 0; j < 4; j++) {
            al |= ((abits >> j) & 1u) << (8*j);
            ah |= ((abits >> (j+4)) & 1u) << (8*j);
        }
        *(uint2*)&s_alpha[0][ry][x0] = make_uint2(al, ah);
        if ((ry == 0 && y > 0) || (ry == 3 && y < 511))
            __stcg((uint2*)(g_alpha[0] + p0), make_uint2(al, ah));
    }
    {
        float mnf = f0[0], mxf = f0[0];
        #pragma unroll
        for (int j = 1; j < 8; j++) { mnf = fminf(mnf, f0[j]); mxf = fmaxf(mxf, f0[j]); }
        #pragma unroll
        for (int j = 0; j < 8; j++) { mnf = fminf(mnf, f1[j]); mxf = fmaxf(mxf, f1[j]); }
        #pragma unroll
        for (int j = 0; j < 8; j++) { mnf = fminf(mnf, f2[j]); mxf = fmaxf(mxf, f2[j]); }
        unsigned mn = __reduce_min_sync(0xFFFFFFFFu, f2ord(mnf));
        unsigned mx = __reduce_max_sync(0xFFFFFFFFu, f2ord(mxf));
        if (lane == 0) { s_u[warp] = mn; s_u[8 + warp] = mx; }
        __syncthreads();
        if (warp == 0) {
            unsigned wmn = (lane < 8) ? s_u[lane]     : 0xFFFFFFFFu;
            unsigned wmx = (lane < 8) ? s_u[8 + lane] : 0u;
            wmn = __reduce_min_sync(0xFFFFFFFFu, wmn);
            wmx = __reduce_max_sync(0xFFFFFFFFu, wmx);
            if (lane == 0) {
                unsigned long long tg = (unsigned long long)(tbase + 15u) << 32;
                st_rel64(&g_mpart[bid][0], tg | wmn);
                st_rel64(&g_mpart[bid][1], tg | wmx);
            }
        }
    }

    // ======== phase 2: poll-gather min/max; normalize + publish tagged sums ========
    {
        if (warp < 2) {
            const unsigned tagm = tbase + 15u;
            unsigned long long v0, v1, v2, v3;
            bool ok;
            do {
                v0 = ld_acq64(&g_mpart[gbase + lane     ][warp]);
                v1 = ld_acq64(&g_mpart[gbase + lane + 32][warp]);
                v2 = ld_acq64(&g_mpart[gbase + lane + 64][warp]);
                v3 = ld_acq64(&g_mpart[gbase + lane + 96][warp]);
                ok = ((unsigned)(v0 >> 32) == tagm) && ((unsigned)(v1 >> 32) == tagm)
                  && ((unsigned)(v2 >> 32) == tagm) && ((unsigned)(v3 >> 32) == tagm);
            } while (!__all_sync(0xFFFFFFFFu, ok));
            unsigned a0 = (unsigned)v0, a1 = (unsigned)v1, a2 = (unsigned)v2, a3 = (unsigned)v3;
            unsigned acc = warp ? max(max(a0, a1), max(a2, a3))
                                : min(min(a0, a1), min(a2, a3));
            acc = warp ? __reduce_max_sync(0xFFFFFFFFu, acc)
                       : __reduce_min_sync(0xFFFFFFFFu, acc);
            if (lane == 0) s_u[warp] = acc;
        }
        __syncthreads();
        const float mnf = ord2f(s_u[0]);
        const float den = __fadd_rn(__fsub_rn(ord2f(s_u[1]), mnf), 1e-12f);

        float s0=0, s1=0, s2=0, cnt=0, u0=0, u1=0, u2=0;
        #pragma unroll
        for (int j = 0; j < 8; j++) {
            f0[j] = normq(f0[j], mnf, den);
            f1[j] = normq(f1[j], mnf, den);
            f2[j] = normq(f2[j], mnf, den);
            unsigned abit = (j < 4) ? ((al >> (8*j)) & 1u) : ((ah >> (8*(j-4))) & 1u);
            float af = abit ? 1.0f : 0.0f;
            s0 = fmaf(f0[j], af, s0); s1 = fmaf(f1[j], af, s1);
            s2 = fmaf(f2[j], af, s2); cnt += af;
            u0 += f0[j]; u1 += f1[j]; u2 += f2[j];
        }
        unsigned v[7] = {(unsigned)s0, (unsigned)s1, (unsigned)s2, (unsigned)cnt,
                         (unsigned)u0, (unsigned)u1, (unsigned)u2};
        #pragma unroll
        for (int j = 0; j < 7; j++) {
            unsigned w = __reduce_add_sync(0xFFFFFFFFu, v[j]);
            if (lane == 0) s_su[j*8 + warp] = w;
        }
        __syncthreads();
        if (warp == 0) {
            unsigned accs[7];
            #pragma unroll
            for (int j = 0; j < 7; j++) {
                unsigned acc = (lane < 8) ? s_su[j*8 + lane] : 0u;
                accs[j] = __reduce_add_sync(0xFFFFFFFFu, acc);
            }
            if (lane < 7)
                st_rel64(&g_spart[0][bid][lane],
                         ((unsigned long long)tbase << 32) | accs[lane]);
        }
    }

    // ======== phase 3: 5 ICM iterations, pure dataflow ========
    #pragma unroll 1
    for (int k = 0; k < 5; k++) {
        const int cur = k & 1, nxt = cur ^ 1;
        const bool last = (k == 4);

        // warps 0-3 (plus 4-6 at k==0): poll-gather this batch's tagged partials
        if (warp < 4 || (k == 0 && warp < 7)) {
            const int kk = (warp < 4) ? k : 0;
            const unsigned tagg = tbase + (unsigned)kk;
            unsigned long long v0, v1, v2, v3;
            bool ok;
            do {
                v0 = ld_acq64(&g_spart[kk][gbase + lane     ][warp]);
                v1 = ld_acq64(&g_spart[kk][gbase + lane + 32][warp]);
                v2 = ld_acq64(&g_spart[kk][gbase + lane + 64][warp]);
                v3 = ld_acq64(&g_spart[kk][gbase + lane + 96][warp]);
                ok = ((unsigned)(v0 >> 32) == tagg) && ((unsigned)(v1 >> 32) == tagg)
                  && ((unsigned)(v2 >> 32) == tagg) && ((unsigned)(v3 >> 32) == tagg);
            } while (!__all_sync(0xFFFFFFFFu, ok));
            unsigned s = (unsigned)v0 + (unsigned)v1 + (unsigned)v2 + (unsigned)v3;
            s = __reduce_add_sync(0xFFFFFFFFu, s);
            if (lane == 0) s_tot[warp] = s;
        }
        // warp 7: wait only on bid+-1's tag, then stage halo rows into smem
        if (warp == 7) {
            const unsigned char* Ab = g_alpha[cur] + bid * 2048;
            const unsigned tagk = tbase + (unsigned)k;
            if (has_up) {
                while ((unsigned)(ld_acq64(&g_spart[k][bid - 1][0]) >> 32) != tagk) {}
                *(uint4*)&s_halo[0][lane*16] = __ldcg((const uint4*)(Ab - 512 + lane*16));
            } else {
                *(uint4*)&s_halo[0][lane*16] = *(const uint4*)&s_alpha[cur][0][lane*16];
            }
            if (has_dn) {
                while ((unsigned)(ld_acq64(&g_spart[k][bid + 1][0]) >> 32) != tagk) {}
                *(uint4*)&s_halo[1][lane*16] = __ldcg((const uint4*)(Ab + 2048 + lane*16));
            } else {
                *(uint4*)&s_halo[1][lane*16] = *(const uint4*)&s_alpha[cur][3][lane*16];
            }
        }
        __syncthreads();
        if (t < 6) {
            float cntf = (float)s_tot[3];
            if (t < 3) {
                s_means[t] = __fdiv_rn((float)s_tot[t], __fadd_rn(cntf, 1e-6f));
            } else {
                unsigned j = t - 3;
                s_means[t] = __fdiv_rn((float)(s_tot[4 + j] - s_tot[j]),
                                       __fadd_rn(__fsub_rn((float)HW, cntf), 1e-6f));
            }
        }
        __syncthreads();
        const float fm0 = s_means[0], fm1 = s_means[1], fm2 = s_means[2];
        const float bm0 = s_means[3], bm1 = s_means[4], bm2 = s_means[5];

        // all neighbor data now in smem
        uint2 up = (ry == 0) ? *(const uint2*)&s_halo[0][x0]
                             : *(const uint2*)&s_alpha[cur][ry-1][x0];
        uint2 dn = (ry == 3) ? *(const uint2*)&s_halo[1][x0]
                             : *(const uint2*)&s_alpha[cur][ry+1][x0];
        unsigned lft = (x0 == 0)   ? (al & 255u)         : (unsigned)s_alpha[cur][ry][x0-1];
        unsigned rgt = (x0 == 504) ? ((ah >> 24) & 255u) : (unsigned)s_alpha[cur][ry][x0+8];

        // byte-SIMD neighbor counts (n per byte in 0..4)
        unsigned lv_lo = (al << 8) | lft;
        unsigned lv_hi = (ah << 8) | (al >> 24);
        unsigned rv_lo = (al >> 8) | (ah << 24);
        unsigned rv_hi = (ah >> 8) | (rgt << 24);
        unsigned n_lo = __vadd4(__vadd4(up.x, dn.x), __vadd4(lv_lo, rv_lo));
        unsigned n_hi = __vadd4(__vadd4(up.y, dn.y), __vadd4(lv_hi, rv_hi));

        unsigned nl = 0, nh = 0;
        float s0 = 0, s1 = 0, s2 = 0, cnt = 0;
        #pragma unroll
        for (int j = 0; j < 8; j++) {
            float i0 = f0[j], i1 = f1[j], i2 = f2[j];
            int n = (int)(((j < 4 ? n_lo : n_hi) >> (8 * (j & 3))) & 255u);
            float pw = (float)(25 * n - 50);       // == 50*(2*(n/4)-1) exactly

            float d0 = __fsub_rn(i0, fm0), d1 = __fsub_rn(i1, fm1), d2 = __fsub_rn(i2, fm2);
            float dfg = __fadd_rn(__fadd_rn(__fmul_rn(d0, d0), __fmul_rn(d1, d1)),
                                  __fmul_rn(d2, d2));
            float e0 = __fsub_rn(i0, bm0), e1 = __fsub_rn(i1, bm1), e2 = __fsub_rn(i2, bm2);
            float dbg = __fadd_rn(__fadd_rn(__fmul_rn(e0, e0), __fmul_rn(e1, e1)),
                                  __fmul_rn(e2, e2));
            float score = __fadd_rn(__fsub_rn(dbg, dfg), pw);

            bool fg = ((fixmask >> j) & 1u) ? (((cenmask >> j) & 1u) != 0u)
                                            : (score > 0.0f);
            unsigned a = fg ? 1u : 0u;
            float af  = fg ? 1.0f : 0.0f;
            if (j < 4) nl |= a << (8*j); else nh |= a << (8*(j-4));
            s0 = fmaf(i0, af, s0); s1 = fmaf(i1, af, s1);
            s2 = fmaf(i2, af, s2); cnt += af;
        }
        al = nl; ah = nh;

        if (!last) {
            // sync before overwriting s_alpha[nxt]: no reader of nxt remains (read 2 iters ago)
            *(uint2*)&s_alpha[nxt][ry][x0] = make_uint2(nl, nh);
            if ((ry == 0 && y > 0) || (ry == 3 && y < 511))
                __stcg((uint2*)(g_alpha[nxt] + p0), make_uint2(nl, nh));

            unsigned v[4] = {(unsigned)s0, (unsigned)s1, (unsigned)s2, (unsigned)cnt};
            #pragma unroll
            for (int j = 0; j < 4; j++) {
                unsigned w = __reduce_add_sync(0xFFFFFFFFu, v[j]);
                if (lane == 0) s_su[j*8 + warp] = w;
            }
            __syncthreads();
            if (warp == 0) {
                unsigned accs[4];
                #pragma unroll
                for (int j = 0; j < 4; j++) {
                    unsigned acc = (lane < 8) ? s_su[j*8 + lane] : 0u;
                    accs[j] = __reduce_add_sync(0xFFFFFFFFu, acc);
                }
                if (lane < 4)
                    st_rel64(&g_spart[k + 1][bid][lane],
                             ((unsigned long long)(tbase + (unsigned)k + 1u) << 32) | accs[lane]);
            }
        } else {
            *(float4*)(out + p0)     = make_float4((float)(nl & 1u),
                                                   (float)((nl >> 8) & 1u),
                                                   (float)((nl >> 16) & 1u),
                                                   (float)((nl >> 24) & 1u));
            *(float4*)(out + p0 + 4) = make_float4((float)(nh & 1u),
                                                   (float)((nh >> 8) & 1u),
                                                   (float)((nh >> 16) & 1u),
                                                   (float)((nh >> 24) & 1u));
        }
    }
}

extern "C" void kernel_launch(void* const* d_in, const int* in_sizes, int n_in,
                              void* d_out, int out_size) {
    const float* feat = (const float*)d_in[0];
    const int*   mask = (const int*)d_in[1];
    float*       out  = (float*)d_out;

    k_init<<<1, 32>>>();
    k_fused<<<GRID, TPB>>>(feat, mask, out);
}

// round 14
// speedup vs baseline: 1.3367x; 1.3367x over previous
#include <cuda_runtime.h>

#define BB 2
#define HH 512
#define WW 512
#define HW (HH*WW)            // 262144
#define CHW ((size_t)256*HW)
#define NPIX (BB*HW)          // 524288
#define GRID 256
#define TPB 256               // 65536 threads, 8 px each; block owns 4 rows

// ---------------- device scratch (static, no allocation) ----------------
__device__ unsigned char g_alpha[2][NPIX];     // only boundary rows actually used
__device__ unsigned g_bar[8][32];              // monotonic per-phase counters (padded lines)
__device__ unsigned g_mpart[GRID][8];          // per-block {mn, mx} (32B padded)
__device__ unsigned g_spart[6][GRID][8];       // per-block {s0,s1,s2,cnt,(t0,t1,t2 @k=0)}

__device__ __forceinline__ unsigned f2ord(float f) {
    unsigned u = __float_as_uint(f);
    return (u & 0x80000000u) ? ~u : (u | 0x80000000u);
}
__device__ __forceinline__ float ord2f(unsigned u) {
    return __uint_as_float((u & 0x80000000u) ? (u ^ 0x80000000u) : ~u);
}
__device__ __forceinline__ float normq(float f, float mn, float den) {
    float v = __fmul_rn(__fdiv_rn(__fsub_rn(f, mn), den), 255.0f);
    v = floorf(v);
    return fminf(fmaxf(v, 0.0f), 255.0f);
}

// self-normalizing monotonic barrier: no reset kernel needed.
// Each replay, counter j starts at a multiple of GRID, so target derives from 'old'.
__device__ __forceinline__ void gridbar(int j) {
    __syncthreads();                       // all threads' stcg stores precede t0's release
    if (threadIdx.x == 0) {
        unsigned long long p = (unsigned long long)__cvta_generic_to_global(&g_bar[j][0]);
        unsigned old;
        asm volatile("atom.release.gpu.global.add.u32 %0, [%1], %2;"
                     : "=r"(old) : "l"(p), "r"(1u) : "memory");
        const unsigned target = (old & ~(unsigned)(GRID - 1)) + (unsigned)GRID;
        unsigned v;
        do {
            asm volatile("ld.acquire.gpu.global.u32 %0, [%1];"
                         : "=r"(v) : "l"(p) : "memory");
        } while (v < target);
    }
    __syncthreads();
}

// ---------------- whole pipeline, ONE kernel, ONE graph node ----------------
__global__ void __launch_bounds__(TPB, 2)
k_fused(const float* __restrict__ feat, const int* __restrict__ mask,
        float* __restrict__ out) {
    const int t    = threadIdx.x;
    const int lane = t & 31, warp = t >> 5;    // 8 warps
    const int bid  = blockIdx.x;
    const int tid  = bid * TPB + t;
    const int p0   = tid * 8;
    const int b    = p0 >> 18;
    const int r    = p0 & (HW - 1);
    const int y    = r >> 9;
    const int x0   = r & 511;
    const int ry   = t >> 6;                   // local row 0..3
    const int gbase = b << 7;                  // first block of this batch

    __shared__ unsigned char s_alpha[2][4][512];   // double-buffered alpha tile
    __shared__ unsigned s_su[7 * 8];
    __shared__ unsigned s_tot[8];
    __shared__ float    s_means[8];
    __shared__ unsigned s_u[16];

    // trimap bitmasks for this thread's 8 px
    unsigned fixmask = 0, cenmask = 0;
    {
        bool yb = (y < 51) | (y >= 461);
        bool yc = (y >= 230) & (y < 281);
        #pragma unroll
        for (int j = 0; j < 8; j++) {
            int xj = x0 + j;
            bool border = yb | (xj < 51) | (xj >= 461);
            bool center = yc & (xj >= 230) & (xj < 281);
            fixmask |= (unsigned)(border | center) << j;
            cenmask |= (unsigned)center << j;
        }
    }

    // ======== phase 1: load pixels + mask; alpha0; per-block min/max ========
    const float* fb = feat + (size_t)b * CHW;
    float f0[8], f1[8], f2[8];
    {
        float4 v;
        v = *(const float4*)(fb + r);              f0[0]=v.x; f0[1]=v.y; f0[2]=v.z; f0[3]=v.w;
        v = *(const float4*)(fb + r + 4);          f0[4]=v.x; f0[5]=v.y; f0[6]=v.z; f0[7]=v.w;
        v = *(const float4*)(fb + HW + r);         f1[0]=v.x; f1[1]=v.y; f1[2]=v.z; f1[3]=v.w;
        v = *(const float4*)(fb + HW + r + 4);     f1[4]=v.x; f1[5]=v.y; f1[6]=v.z; f1[7]=v.w;
        v = *(const float4*)(fb + 2*HW + r);       f2[0]=v.x; f2[1]=v.y; f2[2]=v.z; f2[3]=v.w;
        v = *(const float4*)(fb + 2*HW + r + 4);   f2[4]=v.x; f2[5]=v.y; f2[6]=v.z; f2[7]=v.w;
    }
    unsigned al, ah;                        // own alpha, 8 bytes packed
    {
        int4 m0 = *(const int4*)(mask + p0);
        int4 m1 = *(const int4*)(mask + p0 + 4);
        unsigned mbits =
              (m0.x==1 ? 1u:0u) | (m0.y==1 ? 2u:0u) | (m0.z==1 ? 4u:0u) | (m0.w==1 ? 8u:0u)
            | (m1.x==1 ?16u:0u) | (m1.y==1 ?32u:0u) | (m1.z==1 ?64u:0u) | (m1.w==1?128u:0u);
        unsigned abits = (fixmask & cenmask) | (~fixmask & mbits);   // per-px alpha0 bits
        al = 0; ah = 0;
        #pragma unroll
        for (int j = 0; j < 4; j++) {
            al |= ((abits >> j) & 1u) << (8*j);
            ah |= ((abits >> (j+4)) & 1u) << (8*j);
        }
        *(uint2*)&s_alpha[0][ry][x0] = make_uint2(al, ah);
        if ((ry == 0 && y > 0) || (ry == 3 && y < 511))
            __stcg((uint2*)(g_alpha[0] + p0), make_uint2(al, ah));
    }
    {
        float mnf = f0[0], mxf = f0[0];
        #pragma unroll
        for (int j = 1; j < 8; j++) { mnf = fminf(mnf, f0[j]); mxf = fmaxf(mxf, f0[j]); }
        #pragma unroll
        for (int j = 0; j < 8; j++) { mnf = fminf(mnf, f1[j]); mxf = fmaxf(mxf, f1[j]); }
        #pragma unroll
        for (int j = 0; j < 8; j++) { mnf = fminf(mnf, f2[j]); mxf = fmaxf(mxf, f2[j]); }
        unsigned mn = __reduce_min_sync(0xFFFFFFFFu, f2ord(mnf));
        unsigned mx = __reduce_max_sync(0xFFFFFFFFu, f2ord(mxf));
        if (lane == 0) { s_u[warp] = mn; s_u[8 + warp] = mx; }
        __syncthreads();
        if (warp == 0) {
            unsigned wmn = (lane < 8) ? s_u[lane]     : 0xFFFFFFFFu;
            unsigned wmx = (lane < 8) ? s_u[8 + lane] : 0u;
            wmn = __reduce_min_sync(0xFFFFFFFFu, wmn);
            wmx = __reduce_max_sync(0xFFFFFFFFu, wmx);
            if (lane == 0) {
                __stcg(&g_mpart[bid][0], wmn);
                __stcg(&g_mpart[bid][1], wmx);
            }
        }
    }
    gridbar(0);

    // ======== phase 2: gather min/max; normalize in registers + sums ========
    {
        if (warp < 2) {
            unsigned acc = warp ? 0u : 0xFFFFFFFFu;
            #pragma unroll
            for (int i = 0; i < 4; i++) {
                unsigned v = __ldcg(&g_mpart[gbase + lane + 32*i][warp]);
                acc = warp ? max(acc, v) : min(acc, v);
            }
            acc = warp ? __reduce_max_sync(0xFFFFFFFFu, acc)
                       : __reduce_min_sync(0xFFFFFFFFu, acc);
            if (lane == 0) s_u[warp] = acc;
        }
        __syncthreads();
        const float mnf = ord2f(s_u[0]);
        const float den = __fadd_rn(__fsub_rn(ord2f(s_u[1]), mnf), 1e-12f);

        float s0=0, s1=0, s2=0, cnt=0, u0=0, u1=0, u2=0;
        #pragma unroll
        for (int j = 0; j < 8; j++) {
            f0[j] = normq(f0[j], mnf, den);     // quantized values stay as floats
            f1[j] = normq(f1[j], mnf, den);
            f2[j] = normq(f2[j], mnf, den);
            unsigned abit = (j < 4) ? ((al >> (8*j)) & 1u) : ((ah >> (8*(j-4))) & 1u);
            float af = abit ? 1.0f : 0.0f;
            s0 = fmaf(f0[j], af, s0); s1 = fmaf(f1[j], af, s1);
            s2 = fmaf(f2[j], af, s2); cnt += af;
            u0 += f0[j]; u1 += f1[j]; u2 += f2[j];
        }
        unsigned v[7] = {(unsigned)s0, (unsigned)s1, (unsigned)s2, (unsigned)cnt,
                         (unsigned)u0, (unsigned)u1, (unsigned)u2};
        #pragma unroll
        for (int j = 0; j < 7; j++) {
            unsigned w = __reduce_add_sync(0xFFFFFFFFu, v[j]);
            if (lane == 0) s_su[j*8 + warp] = w;
        }
        __syncthreads();
        if (warp == 0) {
            unsigned accs[7];
            #pragma unroll
            for (int j = 0; j < 7; j++) {
                unsigned acc = (lane < 8) ? s_su[j*8 + lane] : 0u;
                accs[j] = __reduce_add_sync(0xFFFFFFFFu, acc);
            }
            if (lane < 7) __stcg(&g_spart[0][bid][lane], accs[lane]);
        }
    }
    gridbar(1);

    // ======== phase 3: 5 ICM iterations (rolled loop, small I$ footprint) ========
    #pragma unroll 1
    for (int k = 0; k < 5; k++) {
        const int cur = k & 1, nxt = cur ^ 1;
        const bool last = (k == 4);

        // parallel gather: warp w sums 128 per-block partials of value w
        if (warp < 7) {
            const int kk = (warp < 4) ? k : 0;    // totals live in k=0 slot
            unsigned acc = 0;
            #pragma unroll
            for (int i = 0; i < 4; i++)
                acc += __ldcg(&g_spart[kk][gbase + lane + 32*i][warp]);
            acc = __reduce_add_sync(0xFFFFFFFFu, acc);
            if (lane == 0) s_tot[warp] = acc;
        }
        // neighbor fetch overlapped with gather (s_alpha[cur] synced last iter)
        uint2 up, dn;
        if (ry == 0) up = (y == 0)   ? make_uint2(al, ah)
                                     : __ldcg((const uint2*)(g_alpha[cur] + p0 - WW));
        else         up = *(const uint2*)&s_alpha[cur][ry-1][x0];
        if (ry == 3) dn = (y == 511) ? make_uint2(al, ah)
                                     : __ldcg((const uint2*)(g_alpha[cur] + p0 + WW));
        else         dn = *(const uint2*)&s_alpha[cur][ry+1][x0];
        unsigned lft = (x0 == 0)   ? (al & 255u)         : (unsigned)s_alpha[cur][ry][x0-1];
        unsigned rgt = (x0 == 504) ? ((ah >> 24) & 255u) : (unsigned)s_alpha[cur][ry][x0+8];
        __syncthreads();
        if (t < 6) {
            float cntf = (float)s_tot[3];
            if (t < 3) {
                s_means[t] = __fdiv_rn((float)s_tot[t], __fadd_rn(cntf, 1e-6f));
            } else {
                unsigned j = t - 3;
                s_means[t] = __fdiv_rn((float)(s_tot[4 + j] - s_tot[j]),
                                       __fadd_rn(__fsub_rn((float)HW, cntf), 1e-6f));
            }
        }
        __syncthreads();
        const float fm0 = s_means[0], fm1 = s_means[1], fm2 = s_means[2];
        const float bm0 = s_means[3], bm1 = s_means[4], bm2 = s_means[5];

        // byte-SIMD neighbor counts (n per byte in 0..4)
        unsigned lv_lo = (al << 8) | lft;
        unsigned lv_hi = (ah << 8) | (al >> 24);
        unsigned rv_lo = (al >> 8) | (ah << 24);
        unsigned rv_hi = (ah >> 8) | (rgt << 24);
        unsigned n_lo = __vadd4(__vadd4(up.x, dn.x), __vadd4(lv_lo, rv_lo));
        unsigned n_hi = __vadd4(__vadd4(up.y, dn.y), __vadd4(lv_hi, rv_hi));

        unsigned nl = 0, nh = 0;
        float s0 = 0, s1 = 0, s2 = 0, cnt = 0;
        #pragma unroll
        for (int j = 0; j < 8; j++) {
            float i0 = f0[j], i1 = f1[j], i2 = f2[j];
            int n = (int)(((j < 4 ? n_lo : n_hi) >> (8 * (j & 3))) & 255u);
            float pw = (float)(25 * n - 50);       // == 50*(2*(n/4)-1) exactly

            float d0 = __fsub_rn(i0, fm0), d1 = __fsub_rn(i1, fm1), d2 = __fsub_rn(i2, fm2);
            float dfg = __fadd_rn(__fadd_rn(__fmul_rn(d0, d0), __fmul_rn(d1, d1)),
                                  __fmul_rn(d2, d2));
            float e0 = __fsub_rn(i0, bm0), e1 = __fsub_rn(i1, bm1), e2 = __fsub_rn(i2, bm2);
            float dbg = __fadd_rn(__fadd_rn(__fmul_rn(e0, e0), __fmul_rn(e1, e1)),
                                  __fmul_rn(e2, e2));
            float score = __fadd_rn(__fsub_rn(dbg, dfg), pw);

            bool fg = ((fixmask >> j) & 1u) ? (((cenmask >> j) & 1u) != 0u)
                                            : (score > 0.0f);
            unsigned a = fg ? 1u : 0u;
            float af  = fg ? 1.0f : 0.0f;
            if (j < 4) nl |= a << (8*j); else nh |= a << (8*(j-4));
            s0 = fmaf(i0, af, s0); s1 = fmaf(i1, af, s1);
            s2 = fmaf(i2, af, s2); cnt += af;
        }
        al = nl; ah = nh;

        if (!last) {
            *(uint2*)&s_alpha[nxt][ry][x0] = make_uint2(nl, nh);
            if ((ry == 0 && y > 0) || (ry == 3 && y < 511))
                __stcg((uint2*)(g_alpha[nxt] + p0), make_uint2(nl, nh));

            unsigned v[4] = {(unsigned)s0, (unsigned)s1, (unsigned)s2, (unsigned)cnt};
            #pragma unroll
            for (int j = 0; j < 4; j++) {
                unsigned w = __reduce_add_sync(0xFFFFFFFFu, v[j]);
                if (lane == 0) s_su[j*8 + warp] = w;
            }
            __syncthreads();
            if (warp == 0) {
                unsigned accs[4];
                #pragma unroll
                for (int j = 0; j < 4; j++) {
                    unsigned acc = (lane < 8) ? s_su[j*8 + lane] : 0u;
                    accs[j] = __reduce_add_sync(0xFFFFFFFFu, acc);
                }
                if (lane < 4) __stcg(&g_spart[k+1][bid][lane], accs[lane]);
            }
            gridbar(2 + k);
        } else {
            *(float4*)(out + p0)     = make_float4((float)(nl & 1u),
                                                   (float)((nl >> 8) & 1u),
                                                   (float)((nl >> 16) & 1u),
                                                   (float)((nl >> 24) & 1u));
            *(float4*)(out + p0 + 4) = make_float4((float)(nh & 1u),
                                                   (float)((nh >> 8) & 1u),
                                                   (float)((nh >> 16) & 1u),
                                                   (float)((nh >> 24) & 1u));
        }
    }
}

extern "C" void kernel_launch(void* const* d_in, const int* in_sizes, int n_in,
                              void* d_out, int out_size) {
    const float* feat = (const float*)d_in[0];
    const int*   mask = (const int*)d_in[1];
    float*       out  = (float*)d_out;

    k_fused<<<GRID, TPB>>>(feat, mask, out);
}

// round 15
// speedup vs baseline: 1.3384x; 1.0013x over previous
#include <cuda_runtime.h>

#define BB 2
#define HH 512
#define WW 512
#define HW (HH*WW)            // 262144
#define CHW ((size_t)256*HW)
#define NPIX (BB*HW)          // 524288
#define GRID 256
#define TPB 256               // 65536 threads, 8 px each; block owns 4 rows

// ---------------- device scratch (static, no allocation) ----------------
__device__ unsigned char g_alpha[2][NPIX];     // only boundary rows actually used
__device__ unsigned g_bar[8][32];              // monotonic per-phase counters (padded lines)
__device__ unsigned g_mpart[GRID][8];          // per-block {mn, mx} (32B padded)
__device__ unsigned g_acc[6][BB][8];           // atomic sums: s0,s1,s2,cnt,(t0,t1,t2 @0)

__device__ __forceinline__ unsigned f2ord(float f) {
    unsigned u = __float_as_uint(f);
    return (u & 0x80000000u) ? ~u : (u | 0x80000000u);
}
__device__ __forceinline__ float ord2f(unsigned u) {
    return __uint_as_float((u & 0x80000000u) ? (u ^ 0x80000000u) : ~u);
}
__device__ __forceinline__ float normq(float f, float mn, float den) {
    float v = __fmul_rn(__fdiv_rn(__fsub_rn(f, mn), den), 255.0f);
    v = floorf(v);
    return fminf(fmaxf(v, 0.0f), 255.0f);
}

// self-normalizing monotonic barrier: no reset kernel needed.
__device__ __forceinline__ void gridbar(int j) {
    __syncthreads();                       // all threads' stores/atomics precede t0's release
    if (threadIdx.x == 0) {
        unsigned long long p = (unsigned long long)__cvta_generic_to_global(&g_bar[j][0]);
        unsigned old;
        asm volatile("atom.release.gpu.global.add.u32 %0, [%1], %2;"
                     : "=r"(old) : "l"(p), "r"(1u) : "memory");
        const unsigned target = (old & ~(unsigned)(GRID - 1)) + (unsigned)GRID;
        unsigned v;
        do {
            asm volatile("ld.acquire.gpu.global.u32 %0, [%1];"
                         : "=r"(v) : "l"(p) : "memory");
        } while (v < target);
    }
    __syncthreads();
}

// ---------------- whole pipeline, ONE kernel, ONE graph node ----------------
__global__ void __launch_bounds__(TPB, 2)
k_fused(const float* __restrict__ feat, const int* __restrict__ mask,
        float* __restrict__ out) {
    const int t    = threadIdx.x;
    const int lane = t & 31, warp = t >> 5;    // 8 warps
    const int bid  = blockIdx.x;
    const int tid  = bid * TPB + t;
    const int p0   = tid * 8;
    const int b    = p0 >> 18;
    const int r    = p0 & (HW - 1);
    const int y    = r >> 9;
    const int x0   = r & 511;
    const int ry   = t >> 6;                   // local row 0..3
    const int gbase = b << 7;                  // first block of this batch

    __shared__ unsigned char s_alpha[2][4][512];   // double-buffered alpha tile
    __shared__ unsigned s_su[7 * 8];
    __shared__ unsigned s_u[16];

    // zero this replay's accumulators (ordered before any add by gridbar(0))
    if (bid < 6 * BB * 8 / 2 && t < 2)
        __stcg(&((unsigned*)g_acc)[bid * 2 + t], 0u);

    // trimap bitmasks for this thread's 8 px
    unsigned fixmask = 0, cenmask = 0;
    {
        bool yb = (y < 51) | (y >= 461);
        bool yc = (y >= 230) & (y < 281);
        #pragma unroll
        for (int j = 0; j < 8; j++) {
            int xj = x0 + j;
            bool border = yb | (xj < 51) | (xj >= 461);
            bool center = yc & (xj >= 230) & (xj < 281);
            fixmask |= (unsigned)(border | center) << j;
            cenmask |= (unsigned)center << j;
        }
    }

    // ======== phase 1: load pixels + mask; alpha0; per-block min/max ========
    const float* fb = feat + (size_t)b * CHW;
    float f0[8], f1[8], f2[8];
    {
        float4 v;
        v = *(const float4*)(fb + r);              f0[0]=v.x; f0[1]=v.y; f0[2]=v.z; f0[3]=v.w;
        v = *(const float4*)(fb + r + 4);          f0[4]=v.x; f0[5]=v.y; f0[6]=v.z; f0[7]=v.w;
        v = *(const float4*)(fb + HW + r);         f1[0]=v.x; f1[1]=v.y; f1[2]=v.z; f1[3]=v.w;
        v = *(const float4*)(fb + HW + r + 4);     f1[4]=v.x; f1[5]=v.y; f1[6]=v.z; f1[7]=v.w;
        v = *(const float4*)(fb + 2*HW + r);       f2[0]=v.x; f2[1]=v.y; f2[2]=v.z; f2[3]=v.w;
        v = *(const float4*)(fb + 2*HW + r + 4);   f2[4]=v.x; f2[5]=v.y; f2[6]=v.z; f2[7]=v.w;
    }
    unsigned al, ah;                        // own alpha, 8 bytes packed
    {
        int4 m0 = *(const int4*)(mask + p0);
        int4 m1 = *(const int4*)(mask + p0 + 4);
        unsigned mbits =
              (m0.x==1 ? 1u:0u) | (m0.y==1 ? 2u:0u) | (m0.z==1 ? 4u:0u) | (m0.w==1 ? 8u:0u)
            | (m1.x==1 ?16u:0u) | (m1.y==1 ?32u:0u) | (m1.z==1 ?64u:0u) | (m1.w==1?128u:0u);
        unsigned abits = (fixmask & cenmask) | (~fixmask & mbits);   // per-px alpha0 bits
        al = 0; ah = 0;
        #pragma unroll
        for (int j = 0; j < 4; j++) {
            al |= ((abits >> j) & 1u) << (8*j);
            ah |= ((abits >> (j+4)) & 1u) << (8*j);
        }
        *(uint2*)&s_alpha[0][ry][x0] = make_uint2(al, ah);
        if ((ry == 0 && y > 0) || (ry == 3 && y < 511))
            __stcg((uint2*)(g_alpha[0] + p0), make_uint2(al, ah));
    }
    {
        float mnf = f0[0], mxf = f0[0];
        #pragma unroll
        for (int j = 1; j < 8; j++) { mnf = fminf(mnf, f0[j]); mxf = fmaxf(mxf, f0[j]); }
        #pragma unroll
        for (int j = 0; j < 8; j++) { mnf = fminf(mnf, f1[j]); mxf = fmaxf(mxf, f1[j]); }
        #pragma unroll
        for (int j = 0; j < 8; j++) { mnf = fminf(mnf, f2[j]); mxf = fmaxf(mxf, f2[j]); }
        unsigned mn = __reduce_min_sync(0xFFFFFFFFu, f2ord(mnf));
        unsigned mx = __reduce_max_sync(0xFFFFFFFFu, f2ord(mxf));
        if (lane == 0) { s_u[warp] = mn; s_u[8 + warp] = mx; }
        __syncthreads();
        if (warp == 0) {
            unsigned wmn = (lane < 8) ? s_u[lane]     : 0xFFFFFFFFu;
            unsigned wmx = (lane < 8) ? s_u[8 + lane] : 0u;
            wmn = __reduce_min_sync(0xFFFFFFFFu, wmn);
            wmx = __reduce_max_sync(0xFFFFFFFFu, wmx);
            if (lane == 0) {
                __stcg(&g_mpart[bid][0], wmn);
                __stcg(&g_mpart[bid][1], wmx);
            }
        }
    }
    gridbar(0);

    // ======== phase 2: gather min/max; normalize in registers + atomic sums ========
    {
        if (warp < 2) {
            unsigned acc = warp ? 0u : 0xFFFFFFFFu;
            #pragma unroll
            for (int i = 0; i < 4; i++) {
                unsigned v = __ldcg(&g_mpart[gbase + lane + 32*i][warp]);
                acc = warp ? max(acc, v) : min(acc, v);
            }
            acc = warp ? __reduce_max_sync(0xFFFFFFFFu, acc)
                       : __reduce_min_sync(0xFFFFFFFFu, acc);
            if (lane == 0) s_u[warp] = acc;
        }
        __syncthreads();
        const float mnf = ord2f(s_u[0]);
        const float den = __fadd_rn(__fsub_rn(ord2f(s_u[1]), mnf), 1e-12f);

        float s0=0, s1=0, s2=0, cnt=0, u0=0, u1=0, u2=0;
        #pragma unroll
        for (int j = 0; j < 8; j++) {
            f0[j] = normq(f0[j], mnf, den);     // quantized values stay as floats
            f1[j] = normq(f1[j], mnf, den);
            f2[j] = normq(f2[j], mnf, den);
            unsigned abit = (j < 4) ? ((al >> (8*j)) & 1u) : ((ah >> (8*(j-4))) & 1u);
            float af = abit ? 1.0f : 0.0f;
            s0 = fmaf(f0[j], af, s0); s1 = fmaf(f1[j], af, s1);
            s2 = fmaf(f2[j], af, s2); cnt += af;
            u0 += f0[j]; u1 += f1[j]; u2 += f2[j];
        }
        unsigned v[7] = {(unsigned)s0, (unsigned)s1, (unsigned)s2, (unsigned)cnt,
                         (unsigned)u0, (unsigned)u1, (unsigned)u2};
        #pragma unroll
        for (int j = 0; j < 7; j++) {
            unsigned w = __reduce_add_sync(0xFFFFFFFFu, v[j]);
            if (lane == 0) s_su[j*8 + warp] = w;
        }
        __syncthreads();
        if (warp == 0) {
            unsigned accs[7];
            #pragma unroll
            for (int j = 0; j < 7; j++) {
                unsigned acc = (lane < 8) ? s_su[j*8 + lane] : 0u;
                accs[j] = __reduce_add_sync(0xFFFFFFFFu, acc);
            }
            if (lane < 7) atomicAdd(&g_acc[0][b][lane], accs[lane]);
        }
    }
    gridbar(1);

    // ======== phase 3: 5 ICM iterations (rolled loop) ========
    #pragma unroll 1
    for (int k = 0; k < 5; k++) {
        const int cur = k & 1, nxt = cur ^ 1;
        const bool last = (k == 4);

        // every thread: load final sums directly (2 coalesced 16B lines) + halo
        uint4 sv = __ldcg((const uint4*)&g_acc[k][b][0]);   // s0,s1,s2,cnt
        uint4 tv = __ldcg((const uint4*)&g_acc[0][b][4]);   // t0,t1,t2,-
        uint2 up, dn;
        if (ry == 0) up = (y == 0)   ? make_uint2(al, ah)
                                     : __ldcg((const uint2*)(g_alpha[cur] + p0 - WW));
        else         up = *(const uint2*)&s_alpha[cur][ry-1][x0];
        if (ry == 3) dn = (y == 511) ? make_uint2(al, ah)
                                     : __ldcg((const uint2*)(g_alpha[cur] + p0 + WW));
        else         dn = *(const uint2*)&s_alpha[cur][ry+1][x0];
        unsigned lft = (x0 == 0)   ? (al & 255u)         : (unsigned)s_alpha[cur][ry][x0-1];
        unsigned rgt = (x0 == 504) ? ((ah >> 24) & 255u) : (unsigned)s_alpha[cur][ry][x0+8];

        // means computed redundantly per thread (no smem hop, no extra syncs)
        const float cntf = (float)sv.w;
        const float fgc  = __fadd_rn(cntf, 1e-6f);
        const float bgc  = __fadd_rn(__fsub_rn((float)HW, cntf), 1e-6f);
        const float fm0 = __fdiv_rn((float)sv.x, fgc);
        const float fm1 = __fdiv_rn((float)sv.y, fgc);
        const float fm2 = __fdiv_rn((float)sv.z, fgc);
        const float bm0 = __fdiv_rn((float)(tv.x - sv.x), bgc);
        const float bm1 = __fdiv_rn((float)(tv.y - sv.y), bgc);
        const float bm2 = __fdiv_rn((float)(tv.z - sv.z), bgc);

        // byte-SIMD neighbor counts (n per byte in 0..4)
        unsigned lv_lo = (al << 8) | lft;
        unsigned lv_hi = (ah << 8) | (al >> 24);
        unsigned rv_lo = (al >> 8) | (ah << 24);
        unsigned rv_hi = (ah >> 8) | (rgt << 24);
        unsigned n_lo = __vadd4(__vadd4(up.x, dn.x), __vadd4(lv_lo, rv_lo));
        unsigned n_hi = __vadd4(__vadd4(up.y, dn.y), __vadd4(lv_hi, rv_hi));

        unsigned nl = 0, nh = 0;
        float s0 = 0, s1 = 0, s2 = 0, cnt = 0;
        #pragma unroll
        for (int j = 0; j < 8; j++) {
            float i0 = f0[j], i1 = f1[j], i2 = f2[j];
            int n = (int)(((j < 4 ? n_lo : n_hi) >> (8 * (j & 3))) & 255u);
            float pw = (float)(25 * n - 50);       // == 50*(2*(n/4)-1) exactly

            float d0 = __fsub_rn(i0, fm0), d1 = __fsub_rn(i1, fm1), d2 = __fsub_rn(i2, fm2);
            float dfg = __fadd_rn(__fadd_rn(__fmul_rn(d0, d0), __fmul_rn(d1, d1)),
                                  __fmul_rn(d2, d2));
            float e0 = __fsub_rn(i0, bm0), e1 = __fsub_rn(i1, bm1), e2 = __fsub_rn(i2, bm2);
            float dbg = __fadd_rn(__fadd_rn(__fmul_rn(e0, e0), __fmul_rn(e1, e1)),
                                  __fmul_rn(e2, e2));
            float score = __fadd_rn(__fsub_rn(dbg, dfg), pw);

            bool fg = ((fixmask >> j) & 1u) ? (((cenmask >> j) & 1u) != 0u)
                                            : (score > 0.0f);
            unsigned a = fg ? 1u : 0u;
            float af  = fg ? 1.0f : 0.0f;
            if (j < 4) nl |= a << (8*j); else nh |= a << (8*(j-4));
            s0 = fmaf(i0, af, s0); s1 = fmaf(i1, af, s1);
            s2 = fmaf(i2, af, s2); cnt += af;
        }
        al = nl; ah = nh;

        if (!last) {
            *(uint2*)&s_alpha[nxt][ry][x0] = make_uint2(nl, nh);   // nxt not read this iter
            if ((ry == 0 && y > 0) || (ry == 3 && y < 511))
                __stcg((uint2*)(g_alpha[nxt] + p0), make_uint2(nl, nh));

            unsigned v[4] = {(unsigned)s0, (unsigned)s1, (unsigned)s2, (unsigned)cnt};
            #pragma unroll
            for (int j = 0; j < 4; j++) {
                unsigned w = __reduce_add_sync(0xFFFFFFFFu, v[j]);
                if (lane == 0) s_su[j*8 + warp] = w;
            }
            __syncthreads();
            if (warp == 0) {
                unsigned accs[4];
                #pragma unroll
                for (int j = 0; j < 4; j++) {
                    unsigned acc = (lane < 8) ? s_su[j*8 + lane] : 0u;
                    accs[j] = __reduce_add_sync(0xFFFFFFFFu, acc);
                }
                if (lane < 4) atomicAdd(&g_acc[k+1][b][lane], accs[lane]);
            }
            gridbar(2 + k);
        } else {
            *(float4*)(out + p0)     = make_float4((float)(nl & 1u),
                                                   (float)((nl >> 8) & 1u),
                                                   (float)((nl >> 16) & 1u),
                                                   (float)((nl >> 24) & 1u));
            *(float4*)(out + p0 + 4) = make_float4((float)(nh & 1u),
                                                   (float)((nh >> 8) & 1u),
                                                   (float)((nh >> 16) & 1u),
                                                   (float)((nh >> 24) & 1u));
        }
    }
}

extern "C" void kernel_launch(void* const* d_in, const int* in_sizes, int n_in,
                              void* d_out, int out_size) {
    const float* feat = (const float*)d_in[0];
    const int*   mask = (const int*)d_in[1];
    float*       out  = (float*)d_out;

    k_fused<<<GRID, TPB>>>(feat, mask, out);
}

// round 16
// speedup vs baseline: 1.3771x; 1.0289x over previous
#include <cuda_runtime.h>

#define BB 2
#define HH 512
#define WW 512
#define HW (HH*WW)            // 262144
#define CHW ((size_t)256*HW)
#define NPIX (BB*HW)          // 524288
#define GRID 256
#define HGRID 128             // blocks per batch (interleaved: batch = bid & 1)
#define TPB 256               // 65536 threads, 8 px each; block owns 4 rows

// ---------------- device scratch (static, no allocation) ----------------
__device__ unsigned char g_alpha[2][NPIX];     // only boundary rows actually used
__device__ unsigned g_bar[BB][8][32];          // per-batch monotonic counters (padded)
__device__ unsigned g_mpart[BB][HGRID][8];     // per-block {mn, mx} (32B padded)
__device__ unsigned g_acc[6][BB][8];           // atomic sums: s0,s1,s2,cnt,(t0,t1,t2 @0)

__device__ __forceinline__ unsigned f2ord(float f) {
    unsigned u = __float_as_uint(f);
    return (u & 0x80000000u) ? ~u : (u | 0x80000000u);
}
__device__ __forceinline__ float ord2f(unsigned u) {
    return __uint_as_float((u & 0x80000000u) ? (u ^ 0x80000000u) : ~u);
}
__device__ __forceinline__ float normq(float f, float mn, float den) {
    float v = __fmul_rn(__fdiv_rn(__fsub_rn(f, mn), den), 255.0f);
    v = floorf(v);
    return fminf(fmaxf(v, 0.0f), 255.0f);
}

// per-batch self-normalizing monotonic barrier (128 arrivals); no reset kernel.
__device__ __forceinline__ void gridbar(int b, int j) {
    __syncthreads();                       // all threads' stores/atomics precede t0's release
    if (threadIdx.x == 0) {
        unsigned long long p = (unsigned long long)__cvta_generic_to_global(&g_bar[b][j][0]);
        unsigned old;
        asm volatile("atom.release.gpu.global.add.u32 %0, [%1], %2;"
                     : "=r"(old) : "l"(p), "r"(1u) : "memory");
        const unsigned target = (old & ~(unsigned)(HGRID - 1)) + (unsigned)HGRID;
        unsigned v;
        do {
            asm volatile("ld.acquire.gpu.global.u32 %0, [%1];"
                         : "=r"(v) : "l"(p) : "memory");
        } while (v < target);
    }
    __syncthreads();
}

// ---------------- whole pipeline, ONE kernel, ONE graph node ----------------
__global__ void __launch_bounds__(TPB, 2)
k_fused(const float* __restrict__ feat, const int* __restrict__ mask,
        float* __restrict__ out) {
    const int t    = threadIdx.x;
    const int lane = t & 31, warp = t >> 5;    // 8 warps
    const int bid  = blockIdx.x;
    const int b    = bid & 1;                  // interleaved batches
    const int rblk = bid >> 1;                 // 0..127 within batch
    const int r    = rblk * 2048 + t * 8;      // pixel offset within batch
    const int p0   = b * HW + r;               // global pixel offset
    const int y    = r >> 9;
    const int x0   = r & 511;
    const int ry   = t >> 6;                   // local row 0..3

    __shared__ unsigned char s_alpha[2][4][512];   // double-buffered alpha tile
    __shared__ unsigned s_su[7 * 8];
    __shared__ unsigned s_u[16];

    // zero this batch's accumulators (48 words), ordered before adds by gridbar(b,0)
    if (rblk < 24 && t < 2) {
        int idx = rblk * 2 + t;                // 0..47
        __stcg(&((unsigned*)g_acc)[(idx >> 3) * (BB * 8) + b * 8 + (idx & 7)], 0u);
    }

    // trimap bitmasks for this thread's 8 px
    unsigned fixmask = 0, cenmask = 0;
    {
        bool yb = (y < 51) | (y >= 461);
        bool yc = (y >= 230) & (y < 281);
        #pragma unroll
        for (int j = 0; j < 8; j++) {
            int xj = x0 + j;
            bool border = yb | (xj < 51) | (xj >= 461);
            bool center = yc & (xj >= 230) & (xj < 281);
            fixmask |= (unsigned)(border | center) << j;
            cenmask |= (unsigned)center << j;
        }
    }

    // ======== phase 1: load pixels + mask; alpha0; per-block min/max ========
    const float* fb = feat + (size_t)b * CHW;
    float f0[8], f1[8], f2[8];
    {
        float4 v;
        v = *(const float4*)(fb + r);              f0[0]=v.x; f0[1]=v.y; f0[2]=v.z; f0[3]=v.w;
        v = *(const float4*)(fb + r + 4);          f0[4]=v.x; f0[5]=v.y; f0[6]=v.z; f0[7]=v.w;
        v = *(const float4*)(fb + HW + r);         f1[0]=v.x; f1[1]=v.y; f1[2]=v.z; f1[3]=v.w;
        v = *(const float4*)(fb + HW + r + 4);     f1[4]=v.x; f1[5]=v.y; f1[6]=v.z; f1[7]=v.w;
        v = *(const float4*)(fb + 2*HW + r);       f2[0]=v.x; f2[1]=v.y; f2[2]=v.z; f2[3]=v.w;
        v = *(const float4*)(fb + 2*HW + r + 4);   f2[4]=v.x; f2[5]=v.y; f2[6]=v.z; f2[7]=v.w;
    }
    unsigned al, ah;                        // own alpha, 8 bytes packed
    {
        int4 m0 = *(const int4*)(mask + p0);
        int4 m1 = *(const int4*)(mask + p0 + 4);
        unsigned mbits =
              (m0.x==1 ? 1u:0u) | (m0.y==1 ? 2u:0u) | (m0.z==1 ? 4u:0u) | (m0.w==1 ? 8u:0u)
            | (m1.x==1 ?16u:0u) | (m1.y==1 ?32u:0u) | (m1.z==1 ?64u:0u) | (m1.w==1?128u:0u);
        unsigned abits = (fixmask & cenmask) | (~fixmask & mbits);   // per-px alpha0 bits
        al = 0; ah = 0;
        #pragma unroll
        for (int j = 0; j < 4; j++) {
            al |= ((abits >> j) & 1u) << (8*j);
            ah |= ((abits >> (j+4)) & 1u) << (8*j);
        }
        *(uint2*)&s_alpha[0][ry][x0] = make_uint2(al, ah);
        if ((ry == 0 && y > 0) || (ry == 3 && y < 511))
            __stcg((uint2*)(g_alpha[0] + p0), make_uint2(al, ah));
    }
    {
        float mnf = f0[0], mxf = f0[0];
        #pragma unroll
        for (int j = 1; j < 8; j++) { mnf = fminf(mnf, f0[j]); mxf = fmaxf(mxf, f0[j]); }
        #pragma unroll
        for (int j = 0; j < 8; j++) { mnf = fminf(mnf, f1[j]); mxf = fmaxf(mxf, f1[j]); }
        #pragma unroll
        for (int j = 0; j < 8; j++) { mnf = fminf(mnf, f2[j]); mxf = fmaxf(mxf, f2[j]); }
        unsigned mn = __reduce_min_sync(0xFFFFFFFFu, f2ord(mnf));
        unsigned mx = __reduce_max_sync(0xFFFFFFFFu, f2ord(mxf));
        if (lane == 0) { s_u[warp] = mn; s_u[8 + warp] = mx; }
        __syncthreads();
        if (warp == 0) {
            unsigned wmn = (lane < 8) ? s_u[lane]     : 0xFFFFFFFFu;
            unsigned wmx = (lane < 8) ? s_u[8 + lane] : 0u;
            wmn = __reduce_min_sync(0xFFFFFFFFu, wmn);
            wmx = __reduce_max_sync(0xFFFFFFFFu, wmx);
            if (lane == 0) {
                __stcg(&g_mpart[b][rblk][0], wmn);
                __stcg(&g_mpart[b][rblk][1], wmx);
            }
        }
    }
    gridbar(b, 0);

    // ======== phase 2: gather min/max; normalize in registers + atomic sums ========
    {
        if (warp < 2) {
            unsigned acc = warp ? 0u : 0xFFFFFFFFu;
            #pragma unroll
            for (int i = 0; i < 4; i++) {
                unsigned v = __ldcg(&g_mpart[b][lane + 32*i][warp]);
                acc = warp ? max(acc, v) : min(acc, v);
            }
            acc = warp ? __reduce_max_sync(0xFFFFFFFFu, acc)
                       : __reduce_min_sync(0xFFFFFFFFu, acc);
            if (lane == 0) s_u[warp] = acc;
        }
        __syncthreads();
        const float mnf = ord2f(s_u[0]);
        const float den = __fadd_rn(__fsub_rn(ord2f(s_u[1]), mnf), 1e-12f);

        float s0=0, s1=0, s2=0, cnt=0, u0=0, u1=0, u2=0;
        #pragma unroll
        for (int j = 0; j < 8; j++) {
            f0[j] = normq(f0[j], mnf, den);     // quantized values stay as floats
            f1[j] = normq(f1[j], mnf, den);
            f2[j] = normq(f2[j], mnf, den);
            unsigned abit = (j < 4) ? ((al >> (8*j)) & 1u) : ((ah >> (8*(j-4))) & 1u);
            float af = abit ? 1.0f : 0.0f;
            s0 = fmaf(f0[j], af, s0); s1 = fmaf(f1[j], af, s1);
            s2 = fmaf(f2[j], af, s2); cnt += af;
            u0 += f0[j]; u1 += f1[j]; u2 += f2[j];
        }
        unsigned v[7] = {(unsigned)s0, (unsigned)s1, (unsigned)s2, (unsigned)cnt,
                         (unsigned)u0, (unsigned)u1, (unsigned)u2};
        #pragma unroll
        for (int j = 0; j < 7; j++) {
            unsigned w = __reduce_add_sync(0xFFFFFFFFu, v[j]);
            if (lane == 0) s_su[j*8 + warp] = w;
        }
        __syncthreads();
        if (warp == 0) {
            unsigned accs[7];
            #pragma unroll
            for (int j = 0; j < 7; j++) {
                unsigned acc = (lane < 8) ? s_su[j*8 + lane] : 0u;
                accs[j] = __reduce_add_sync(0xFFFFFFFFu, acc);
            }
            if (lane < 7) atomicAdd(&g_acc[0][b][lane], accs[lane]);
        }
    }
    gridbar(b, 1);

    // ======== phase 3: 5 ICM iterations (rolled loop) ========
    #pragma unroll 1
    for (int k = 0; k < 5; k++) {
        const int cur = k & 1, nxt = cur ^ 1;
        const bool last = (k == 4);

        // every thread: load final sums directly (2 coalesced 16B lines) + halo
        uint4 sv = __ldcg((const uint4*)&g_acc[k][b][0]);   // s0,s1,s2,cnt
        uint4 tv = __ldcg((const uint4*)&g_acc[0][b][4]);   // t0,t1,t2,-
        uint2 up, dn;
        if (ry == 0) up = (y == 0)   ? make_uint2(al, ah)
                                     : __ldcg((const uint2*)(g_alpha[cur] + p0 - WW));
        else         up = *(const uint2*)&s_alpha[cur][ry-1][x0];
        if (ry == 3) dn = (y == 511) ? make_uint2(al, ah)
                                     : __ldcg((const uint2*)(g_alpha[cur] + p0 + WW));
        else         dn = *(const uint2*)&s_alpha[cur][ry+1][x0];
        unsigned lft = (x0 == 0)   ? (al & 255u)         : (unsigned)s_alpha[cur][ry][x0-1];
        unsigned rgt = (x0 == 504) ? ((ah >> 24) & 255u) : (unsigned)s_alpha[cur][ry][x0+8];

        // means computed redundantly per thread (no smem hop, no extra syncs)
        const float cntf = (float)sv.w;
        const float fgc  = __fadd_rn(cntf, 1e-6f);
        const float bgc  = __fadd_rn(__fsub_rn((float)HW, cntf), 1e-6f);
        const float fm0 = __fdiv_rn((float)sv.x, fgc);
        const float fm1 = __fdiv_rn((float)sv.y, fgc);
        const float fm2 = __fdiv_rn((float)sv.z, fgc);
        const float bm0 = __fdiv_rn((float)(tv.x - sv.x), bgc);
        const float bm1 = __fdiv_rn((float)(tv.y - sv.y), bgc);
        const float bm2 = __fdiv_rn((float)(tv.z - sv.z), bgc);

        // byte-SIMD neighbor counts (n per byte in 0..4)
        unsigned lv_lo = (al << 8) | lft;
        unsigned lv_hi = (ah << 8) | (al >> 24);
        unsigned rv_lo = (al >> 8) | (ah << 24);
        unsigned rv_hi = (ah >> 8) | (rgt << 24);
        unsigned n_lo = __vadd4(__vadd4(up.x, dn.x), __vadd4(lv_lo, rv_lo));
        unsigned n_hi = __vadd4(__vadd4(up.y, dn.y), __vadd4(lv_hi, rv_hi));

        unsigned nl = 0, nh = 0;
        float s0 = 0, s1 = 0, s2 = 0, cnt = 0;
        #pragma unroll
        for (int j = 0; j < 8; j++) {
            float i0 = f0[j], i1 = f1[j], i2 = f2[j];
            int n = (int)(((j < 4 ? n_lo : n_hi) >> (8 * (j & 3))) & 255u);
            float pw = (float)(25 * n - 50);       // == 50*(2*(n/4)-1) exactly

            float d0 = __fsub_rn(i0, fm0), d1 = __fsub_rn(i1, fm1), d2 = __fsub_rn(i2, fm2);
            float dfg = __fadd_rn(__fadd_rn(__fmul_rn(d0, d0), __fmul_rn(d1, d1)),
                                  __fmul_rn(d2, d2));
            float e0 = __fsub_rn(i0, bm0), e1 = __fsub_rn(i1, bm1), e2 = __fsub_rn(i2, bm2);
            float dbg = __fadd_rn(__fadd_rn(__fmul_rn(e0, e0), __fmul_rn(e1, e1)),
                                  __fmul_rn(e2, e2));
            float score = __fadd_rn(__fsub_rn(dbg, dfg), pw);

            bool fg = ((fixmask >> j) & 1u) ? (((cenmask >> j) & 1u) != 0u)
                                            : (score > 0.0f);
            unsigned a = fg ? 1u : 0u;
            float af  = fg ? 1.0f : 0.0f;
            if (j < 4) nl |= a << (8*j); else nh |= a << (8*(j-4));
            s0 = fmaf(i0, af, s0); s1 = fmaf(i1, af, s1);
            s2 = fmaf(i2, af, s2); cnt += af;
        }
        al = nl; ah = nh;

        if (!last) {
            *(uint2*)&s_alpha[nxt][ry][x0] = make_uint2(nl, nh);   // nxt not read this iter
            if ((ry == 0 && y > 0) || (ry == 3 && y < 511))
                __stcg((uint2*)(g_alpha[nxt] + p0), make_uint2(nl, nh));

            unsigned v[4] = {(unsigned)s0, (unsigned)s1, (unsigned)s2, (unsigned)cnt};
            #pragma unroll
            for (int j = 0; j < 4; j++) {
                unsigned w = __reduce_add_sync(0xFFFFFFFFu, v[j]);
                if (lane == 0) s_su[j*8 + warp] = w;
            }
            __syncthreads();
            if (warp == 0) {
                unsigned accs[4];
                #pragma unroll
                for (int j = 0; j < 4; j++) {
                    unsigned acc = (lane < 8) ? s_su[j*8 + lane] : 0u;
                    accs[j] = __reduce_add_sync(0xFFFFFFFFu, acc);
                }
                if (lane < 4) atomicAdd(&g_acc[k+1][b][lane], accs[lane]);
            }
            gridbar(b, 2 + k);
        } else {
            *(float4*)(out + p0)     = make_float4((float)(nl & 1u),
                                                   (float)((nl >> 8) & 1u),
                                                   (float)((nl >> 16) & 1u),
                                                   (float)((nl >> 24) & 1u));
            *(float4*)(out + p0 + 4) = make_float4((float)(nh & 1u),
                                                   (float)((nh >> 8) & 1u),
                                                   (float)((nh >> 16) & 1u),
                                                   (float)((nh >> 24) & 1u));
        }
    }
}

extern "C" void kernel_launch(void* const* d_in, const int* in_sizes, int n_in,
                              void* d_out, int out_size) {
    const float* feat = (const float*)d_in[0];
    const int*   mask = (const int*)d_in[1];
    float*       out  = (float*)d_out;

    k_fused<<<GRID, TPB>>>(feat, mask, out);
}